// round 2
// baseline (speedup 1.0000x reference)
#include <cuda_runtime.h>

#define BATCH 2
#define NV    4096
#define NF    4096
#define IMG_H 256
#define IMG_W 256

// ---------------------------------------------------------------------------
// Single fused kernel: per-pixel coverage (mask = OR over triangles), with
// on-the-fly vertex transform. All per-triangle loads are warp-uniform ->
// broadcast from L1. Early exit after the first covering triangle.
// Arithmetic expression order matches the reference (rel_err must stay 0).
// ---------------------------------------------------------------------------
__global__ void __launch_bounds__(256) fused_raster(
    const float* __restrict__ verts,   // [B,NV,3]
    const int*   __restrict__ faces,   // [B,NF,3]
    const float* __restrict__ Rm,      // [B,3,3]
    const float* __restrict__ Tm,      // [B,3]
    float*       __restrict__ out)     // [B,H,W,3]
{
    int pix = blockIdx.x * blockDim.x + threadIdx.x;
    if (pix >= BATCH * IMG_H * IMG_W) return;

    int b = pix / (IMG_H * IMG_W);
    int r = pix - b * (IMG_H * IMG_W);
    int y = r / IMG_W;
    int x = r - y * IMG_W;

    // pixel center in ndc, same expression order as reference
    float px = (((float)x + 0.5f) / (float)IMG_W) * 2.0f - 1.0f;
    float py = (((float)y + 0.5f) / (float)IMG_H) * 2.0f - 1.0f;

    // ---- build VP rows for this batch (identical ordering to R1 kernel) ----
    const float* R = Rm + b * 9;
    const float* T = Tm + b * 3;

    float t0 = -((R[0] * T[0] + R[3] * T[1]) + R[6] * T[2]);
    float t1 = -((R[1] * T[0] + R[4] * T[1]) + R[7] * T[2]);
    float t2 = -((R[2] * T[0] + R[5] * T[1]) + R[8] * T[2]);

    const float f = 1.7320508075688772f;   // 1/tan(30 deg)

    float VP00 = f * R[0], VP01 = f * R[3], VP02 = f * R[6], VP03 = f * t0;
    float VP10 = f * R[1], VP11 = f * R[4], VP12 = f * R[7], VP13 = f * t1;
    float VP30 = -R[2],    VP31 = -R[5],    VP32 = -R[8],    VP33 = -t2;

    const int*   fb = faces + b * NF * 3;
    const float* vb = verts + b * NV * 3;

    float covered = 0.0f;
    for (int t = 0; t < NF; ++t) {
        // warp-uniform loads (all lanes read the same addresses)
        int i0 = __ldg(&fb[t * 3 + 0]);
        int i1 = __ldg(&fb[t * 3 + 1]);
        int i2 = __ldg(&fb[t * 3 + 2]);

        // transform vertex 0
        float a0 = __ldg(&vb[i0 * 3 + 0]);
        float a1 = __ldg(&vb[i0 * 3 + 1]);
        float a2 = __ldg(&vb[i0 * 3 + 2]);
        float c0x = ((a0 * VP00 + a1 * VP01) + a2 * VP02) + VP03;
        float c0y = ((a0 * VP10 + a1 * VP11) + a2 * VP12) + VP13;
        float c0w = ((a0 * VP30 + a1 * VP31) + a2 * VP32) + VP33;
        float w0 = fmaxf(c0w, 1e-8f);
        float x0 = c0x / w0, y0 = c0y / w0;

        // vertex 1
        float b0 = __ldg(&vb[i1 * 3 + 0]);
        float b1 = __ldg(&vb[i1 * 3 + 1]);
        float b2 = __ldg(&vb[i1 * 3 + 2]);
        float c1x = ((b0 * VP00 + b1 * VP01) + b2 * VP02) + VP03;
        float c1y = ((b0 * VP10 + b1 * VP11) + b2 * VP12) + VP13;
        float c1w = ((b0 * VP30 + b1 * VP31) + b2 * VP32) + VP33;
        float w1 = fmaxf(c1w, 1e-8f);
        float x1 = c1x / w1, y1 = c1y / w1;

        // vertex 2
        float d0 = __ldg(&vb[i2 * 3 + 0]);
        float d1 = __ldg(&vb[i2 * 3 + 1]);
        float d2 = __ldg(&vb[i2 * 3 + 2]);
        float c2x = ((d0 * VP00 + d1 * VP01) + d2 * VP02) + VP03;
        float c2y = ((d0 * VP10 + d1 * VP11) + d2 * VP12) + VP13;
        float c2w = ((d0 * VP30 + d1 * VP31) + d2 * VP32) + VP33;
        float w2 = fmaxf(c2w, 1e-8f);
        float x2 = c2x / w2, y2 = c2y / w2;

        // edge functions (same order as reference)
        float e0 = (x1 - x0) * (py - y0) - (y1 - y0) * (px - x0);
        float e1 = (x2 - x1) * (py - y1) - (y2 - y1) * (px - x1);
        float e2 = (x0 - x2) * (py - y2) - (y0 - y2) * (px - x2);

        bool pos = (e0 >= 0.0f) & (e1 >= 0.0f) & (e2 >= 0.0f);
        bool neg = (e0 <= 0.0f) & (e1 <= 0.0f) & (e2 <= 0.0f);
        if (pos | neg) { covered = 1.0f; break; }
    }

    float* o = out + (size_t)pix * 3;
    o[0] = covered;
    o[1] = covered;
    o[2] = covered;
}

// ---------------------------------------------------------------------------
extern "C" void kernel_launch(void* const* d_in, const int* in_sizes, int n_in,
                              void* d_out, int out_size) {
    const float* verts = (const float*)d_in[0];   // [2,4096,3]
    const int*   faces = (const int*)  d_in[1];   // [2,4096,3]
    const float* Rm    = (const float*)d_in[2];   // [2,3,3]
    const float* Tm    = (const float*)d_in[3];   // [2,3]
    float* out = (float*)d_out;                   // [2,256,256,3]

    int total = BATCH * IMG_H * IMG_W;
    fused_raster<<<(total + 255) / 256, 256>>>(verts, faces, Rm, Tm, out);
}

// round 3
// speedup vs baseline: 2.1287x; 2.1287x over previous
#include <cuda_runtime.h>

#define BATCH 2
#define NV    4096
#define NF    4096
#define IMG_H 256
#define IMG_W 256
#define CHUNK 128

// ---------------------------------------------------------------------------
// Single kernel, block-cooperative:
//   block = one image row (256 pixels). Threads 0..127 stage a chunk of 128
//   transformed triangles into smem; all 256 threads then test their pixel
//   against the chunk (broadcast LDS, 12 FLOPs/tri) with early exit; a block
//   vote terminates once every pixel in the row is covered.
// Expression order matches the reference-passing kernels (rel_err == 0).
// ---------------------------------------------------------------------------
__global__ void __launch_bounds__(256) raster_block(
    const float* __restrict__ verts,   // [B,NV,3]
    const int*   __restrict__ faces,   // [B,NF,3]
    const float* __restrict__ Rm,      // [B,3,3]
    const float* __restrict__ Tm,      // [B,3]
    float*       __restrict__ out)     // [B,H,W,3]
{
    __shared__ float4 sA[CHUNK];   // x0,y0,x1,y1
    __shared__ float4 sC[CHUNK];   // x2,y2,-,-

    int b = blockIdx.x >> 8;          // / IMG_H
    int y = blockIdx.x & (IMG_H - 1);
    int x = threadIdx.x;

    // pixel center in ndc (same expression order as reference)
    float px = (((float)x + 0.5f) / (float)IMG_W) * 2.0f - 1.0f;
    float py = (((float)y + 0.5f) / (float)IMG_H) * 2.0f - 1.0f;

    // ---- VP rows for this batch (uniform loads; identical ordering) ----
    const float* R = Rm + b * 9;
    const float* T = Tm + b * 3;

    float t0 = -((R[0] * T[0] + R[3] * T[1]) + R[6] * T[2]);
    float t1 = -((R[1] * T[0] + R[4] * T[1]) + R[7] * T[2]);
    float t2 = -((R[2] * T[0] + R[5] * T[1]) + R[8] * T[2]);

    const float f = 1.7320508075688772f;   // 1/tan(30 deg)

    float VP00 = f * R[0], VP01 = f * R[3], VP02 = f * R[6], VP03 = f * t0;
    float VP10 = f * R[1], VP11 = f * R[4], VP12 = f * R[7], VP13 = f * t1;
    float VP30 = -R[2],    VP31 = -R[5],    VP32 = -R[8],    VP33 = -t2;

    const int*   fb = faces + b * NF * 3;
    const float* vb = verts + b * NV * 3;

    float covered = 0.0f;

    for (int ct = 0; ct < NF / CHUNK; ++ct) {
        // ---- stage chunk: threads 0..127 transform one triangle each ----
        if (threadIdx.x < CHUNK) {
            int t = ct * CHUNK + threadIdx.x;
            int i0 = __ldg(&fb[t * 3 + 0]);
            int i1 = __ldg(&fb[t * 3 + 1]);
            int i2 = __ldg(&fb[t * 3 + 2]);

            float a0 = __ldg(&vb[i0 * 3 + 0]);
            float a1 = __ldg(&vb[i0 * 3 + 1]);
            float a2 = __ldg(&vb[i0 * 3 + 2]);
            float c0x = ((a0 * VP00 + a1 * VP01) + a2 * VP02) + VP03;
            float c0y = ((a0 * VP10 + a1 * VP11) + a2 * VP12) + VP13;
            float c0w = ((a0 * VP30 + a1 * VP31) + a2 * VP32) + VP33;
            float w0 = fmaxf(c0w, 1e-8f);
            float x0 = c0x / w0, y0 = c0y / w0;

            float b0 = __ldg(&vb[i1 * 3 + 0]);
            float b1 = __ldg(&vb[i1 * 3 + 1]);
            float b2 = __ldg(&vb[i1 * 3 + 2]);
            float c1x = ((b0 * VP00 + b1 * VP01) + b2 * VP02) + VP03;
            float c1y = ((b0 * VP10 + b1 * VP11) + b2 * VP12) + VP13;
            float c1w = ((b0 * VP30 + b1 * VP31) + b2 * VP32) + VP33;
            float w1 = fmaxf(c1w, 1e-8f);
            float x1 = c1x / w1, y1 = c1y / w1;

            float d0 = __ldg(&vb[i2 * 3 + 0]);
            float d1 = __ldg(&vb[i2 * 3 + 1]);
            float d2 = __ldg(&vb[i2 * 3 + 2]);
            float c2x = ((d0 * VP00 + d1 * VP01) + d2 * VP02) + VP03;
            float c2y = ((d0 * VP10 + d1 * VP11) + d2 * VP12) + VP13;
            float c2w = ((d0 * VP30 + d1 * VP31) + d2 * VP32) + VP33;
            float w2 = fmaxf(c2w, 1e-8f);
            float x2 = c2x / w2, y2 = c2y / w2;

            sA[threadIdx.x] = make_float4(x0, y0, x1, y1);
            sC[threadIdx.x] = make_float4(x2, y2, 0.0f, 0.0f);
        }
        __syncthreads();

        // ---- test this pixel against the staged chunk ----
        if (covered == 0.0f) {
            #pragma unroll 4
            for (int i = 0; i < CHUNK; ++i) {
                float4 A = sA[i];
                float4 C = sC[i];
                float e0 = (A.z - A.x) * (py - A.y) - (A.w - A.y) * (px - A.x);
                float e1 = (C.x - A.z) * (py - A.w) - (C.y - A.w) * (px - A.z);
                float e2 = (A.x - C.x) * (py - C.y) - (A.y - C.y) * (px - C.x);
                bool pos = (e0 >= 0.0f) & (e1 >= 0.0f) & (e2 >= 0.0f);
                bool neg = (e0 <= 0.0f) & (e1 <= 0.0f) & (e2 <= 0.0f);
                if (pos | neg) { covered = 1.0f; break; }
            }
        }

        // full barrier + vote: safe to overwrite smem next iter, and break
        // the whole block once every pixel in the row is covered.
        if (__syncthreads_and(covered != 0.0f)) break;
    }

    int pix = (b * IMG_H + y) * IMG_W + x;
    float* o = out + (size_t)pix * 3;
    o[0] = covered;
    o[1] = covered;
    o[2] = covered;
}

// ---------------------------------------------------------------------------
extern "C" void kernel_launch(void* const* d_in, const int* in_sizes, int n_in,
                              void* d_out, int out_size) {
    const float* verts = (const float*)d_in[0];   // [2,4096,3]
    const int*   faces = (const int*)  d_in[1];   // [2,4096,3]
    const float* Rm    = (const float*)d_in[2];   // [2,3,3]
    const float* Tm    = (const float*)d_in[3];   // [2,3]
    float* out = (float*)d_out;                   // [2,256,256,3]

    raster_block<<<BATCH * IMG_H, 256>>>(verts, faces, Rm, Tm, out);
}

// round 4
// speedup vs baseline: 2.1365x; 1.0037x over previous
#include <cuda_runtime.h>

#define BATCH 2
#define NV    4096
#define NF    4096
#define IMG_H 256
#define IMG_W 256
#define CHUNK 128

// ---------------------------------------------------------------------------
// Block = one image row (256 px). Staging threads (0..127) transform a chunk
// of 128 triangles into smem. During staging each triangle is also tested
// against the 4 extreme pixel centers with a large margin: edge functions are
// affine in (px,py), so all-4-corners inside with margin 1e12 guarantees the
// exact per-pixel fp test passes at EVERY pixel (rounding noise is <= ~1e9
// at these magnitudes). Such a triangle makes the whole image 1s -> block
// writes 1 and exits without running the per-pixel loop. Fallback path is
// bit-identical to the R3 kernel (rel_err == 0).
// ---------------------------------------------------------------------------
__global__ void __launch_bounds__(256) raster_block(
    const float* __restrict__ verts,   // [B,NV,3]
    const int*   __restrict__ faces,   // [B,NF,3]
    const float* __restrict__ Rm,      // [B,3,3]
    const float* __restrict__ Tm,      // [B,3]
    float*       __restrict__ out)     // [B,H,W,3]
{
    __shared__ float4 sA[CHUNK];   // x0,y0,x1,y1
    __shared__ float4 sC[CHUNK];   // x2,y2,-,-
    __shared__ int    s_full;      // a staged triangle provably covers screen

    int b = blockIdx.x >> 8;          // / IMG_H
    int y = blockIdx.x & (IMG_H - 1);
    int x = threadIdx.x;

    // pixel center in ndc (same expression order as reference)
    float px = (((float)x + 0.5f) / (float)IMG_W) * 2.0f - 1.0f;
    float py = (((float)y + 0.5f) / (float)IMG_H) * 2.0f - 1.0f;

    // extreme pixel centers (exactly representable)
    const float cx0 = ((0.0f + 0.5f) / (float)IMG_W) * 2.0f - 1.0f;
    const float cx1 = ((255.0f + 0.5f) / (float)IMG_W) * 2.0f - 1.0f;
    const float cy0 = ((0.0f + 0.5f) / (float)IMG_H) * 2.0f - 1.0f;
    const float cy1 = ((255.0f + 0.5f) / (float)IMG_H) * 2.0f - 1.0f;
    const float MARGIN = 1e12f;

    if (threadIdx.x == 0) s_full = 0;

    // ---- VP rows for this batch (uniform loads; identical ordering) ----
    const float* R = Rm + b * 9;
    const float* T = Tm + b * 3;

    float t0 = -((R[0] * T[0] + R[3] * T[1]) + R[6] * T[2]);
    float t1 = -((R[1] * T[0] + R[4] * T[1]) + R[7] * T[2]);
    float t2 = -((R[2] * T[0] + R[5] * T[1]) + R[8] * T[2]);

    const float f = 1.7320508075688772f;   // 1/tan(30 deg)

    float VP00 = f * R[0], VP01 = f * R[3], VP02 = f * R[6], VP03 = f * t0;
    float VP10 = f * R[1], VP11 = f * R[4], VP12 = f * R[7], VP13 = f * t1;
    float VP30 = -R[2],    VP31 = -R[5],    VP32 = -R[8],    VP33 = -t2;

    const int*   fb = faces + b * NF * 3;
    const float* vb = verts + b * NV * 3;

    float covered = 0.0f;

    __syncthreads();   // order s_full init before any staging write

    for (int ct = 0; ct < NF / CHUNK; ++ct) {
        // ---- stage chunk: threads 0..127 transform one triangle each ----
        if (threadIdx.x < CHUNK) {
            int t = ct * CHUNK + threadIdx.x;
            int i0 = __ldg(&fb[t * 3 + 0]);
            int i1 = __ldg(&fb[t * 3 + 1]);
            int i2 = __ldg(&fb[t * 3 + 2]);

            float a0 = __ldg(&vb[i0 * 3 + 0]);
            float a1 = __ldg(&vb[i0 * 3 + 1]);
            float a2 = __ldg(&vb[i0 * 3 + 2]);
            float c0x = ((a0 * VP00 + a1 * VP01) + a2 * VP02) + VP03;
            float c0y = ((a0 * VP10 + a1 * VP11) + a2 * VP12) + VP13;
            float c0w = ((a0 * VP30 + a1 * VP31) + a2 * VP32) + VP33;
            float w0 = fmaxf(c0w, 1e-8f);
            float x0 = c0x / w0, y0 = c0y / w0;

            float b0 = __ldg(&vb[i1 * 3 + 0]);
            float b1 = __ldg(&vb[i1 * 3 + 1]);
            float b2 = __ldg(&vb[i1 * 3 + 2]);
            float c1x = ((b0 * VP00 + b1 * VP01) + b2 * VP02) + VP03;
            float c1y = ((b0 * VP10 + b1 * VP11) + b2 * VP12) + VP13;
            float c1w = ((b0 * VP30 + b1 * VP31) + b2 * VP32) + VP33;
            float w1 = fmaxf(c1w, 1e-8f);
            float x1 = c1x / w1, y1 = c1y / w1;

            float d0 = __ldg(&vb[i2 * 3 + 0]);
            float d1 = __ldg(&vb[i2 * 3 + 1]);
            float d2 = __ldg(&vb[i2 * 3 + 2]);
            float c2x = ((d0 * VP00 + d1 * VP01) + d2 * VP02) + VP03;
            float c2y = ((d0 * VP10 + d1 * VP11) + d2 * VP12) + VP13;
            float c2w = ((d0 * VP30 + d1 * VP31) + d2 * VP32) + VP33;
            float w2 = fmaxf(c2w, 1e-8f);
            float x2 = c2x / w2, y2 = c2y / w2;

            sA[threadIdx.x] = make_float4(x0, y0, x1, y1);
            sC[threadIdx.x] = make_float4(x2, y2, 0.0f, 0.0f);

            // ---- margin-safe full-screen test at the 4 extreme centers ----
            bool posAll = true, negAll = true;
            #pragma unroll
            for (int c = 0; c < 4; ++c) {
                float cx = (c & 1) ? cx1 : cx0;
                float cy = (c & 2) ? cy1 : cy0;
                float e0 = (x1 - x0) * (cy - y0) - (y1 - y0) * (cx - x0);
                float e1 = (x2 - x1) * (cy - y1) - (y2 - y1) * (cx - x1);
                float e2 = (x0 - x2) * (cy - y2) - (y0 - y2) * (cx - x2);
                posAll = posAll & (e0 >=  MARGIN) & (e1 >=  MARGIN) & (e2 >=  MARGIN);
                negAll = negAll & (e0 <= -MARGIN) & (e1 <= -MARGIN) & (e2 <= -MARGIN);
            }
            if (posAll | negAll) s_full = 1;
        }
        __syncthreads();

        // whole screen provably covered -> every pixel is 1, done.
        if (s_full) { covered = 1.0f; break; }

        // ---- test this pixel against the staged chunk (exact path) ----
        if (covered == 0.0f) {
            #pragma unroll 4
            for (int i = 0; i < CHUNK; ++i) {
                float4 A = sA[i];
                float4 C = sC[i];
                float e0 = (A.z - A.x) * (py - A.y) - (A.w - A.y) * (px - A.x);
                float e1 = (C.x - A.z) * (py - A.w) - (C.y - A.w) * (px - A.z);
                float e2 = (A.x - C.x) * (py - C.y) - (A.y - C.y) * (px - C.x);
                bool pos = (e0 >= 0.0f) & (e1 >= 0.0f) & (e2 >= 0.0f);
                bool neg = (e0 <= 0.0f) & (e1 <= 0.0f) & (e2 <= 0.0f);
                if (pos | neg) { covered = 1.0f; break; }
            }
        }

        if (__syncthreads_and(covered != 0.0f)) break;
    }

    int pix = (b * IMG_H + y) * IMG_W + x;
    float* o = out + (size_t)pix * 3;
    o[0] = covered;
    o[1] = covered;
    o[2] = covered;
}

// ---------------------------------------------------------------------------
extern "C" void kernel_launch(void* const* d_in, const int* in_sizes, int n_in,
                              void* d_out, int out_size) {
    const float* verts = (const float*)d_in[0];   // [2,4096,3]
    const int*   faces = (const int*)  d_in[1];   // [2,4096,3]
    const float* Rm    = (const float*)d_in[2];   // [2,3,3]
    const float* Tm    = (const float*)d_in[3];   // [2,3]
    float* out = (float*)d_out;                   // [2,256,256,3]

    raster_block<<<BATCH * IMG_H, 256>>>(verts, faces, Rm, Tm, out);
}